// round 1
// baseline (speedup 1.0000x reference)
#include <cuda_runtime.h>
#include <math.h>

// Problem constants
#define B_  10
#define T_  2048
#define I_  128
#define H_  256
#define L_  6
#define G4  (4 * H_)      // 1024 gate rows per layer

// Kernel config
#define NBLK     24        // blocks per layer
#define THREADS  256
#define KSTRIDE  524       // padded row stride (floats); 524 % 32 == 12 -> <=2-way conflicts
#define ROWS_MAX 44        // 4 * ceil(256/24)
#define JC_MAX   11

// Scratch (device globals: allocation-free contract)
// hseq[l][t][b][h] for t = 0..T (t=0 is h0)
__device__ float g_hseq[(size_t)L_ * (T_ + 1) * B_ * H_];
__device__ int   g_counter[L_ * (T_ + 1)];

__global__ void lstm_init_kernel(const float* __restrict__ h0) {
    int tid = blockIdx.x * blockDim.x + threadIdx.x;
    // copy h0 -> hseq[:, 0, :, :]
    if (tid < L_ * B_ * H_) {
        int l = tid / (B_ * H_);
        int rem = tid - l * (B_ * H_);
        g_hseq[((size_t)l * (T_ + 1)) * B_ * H_ + rem] = h0[tid];
    }
    // reset counters; t=0 slot is "complete"
    if (tid < L_ * (T_ + 1)) {
        g_counter[tid] = ((tid % (T_ + 1)) == 0) ? NBLK : 0;
    }
}

__device__ __forceinline__ float sigmoidf_fast(float x) {
    return 1.0f / (1.0f + __expf(-x));
}

__global__ void __launch_bounds__(THREADS, 1)
lstm_pipeline_kernel(const float* __restrict__ x,
                     const float* __restrict__ c0,
                     const float* __restrict__ Wih0,
                     const float* __restrict__ Wih,   // [L-1][4H][H]
                     const float* __restrict__ Whh,   // [L][4H][H]
                     const float* __restrict__ bih,   // [L][4H]
                     const float* __restrict__ bhh,   // [L][4H]
                     float* __restrict__ out)         // [L][B][H]
{
    extern __shared__ float sm[];

    const int l     = blockIdx.x / NBLK;
    const int p     = blockIdx.x % NBLK;
    const int jbase = (p * H_) / NBLK;
    const int jend  = ((p + 1) * H_) / NBLK;
    const int jc    = jend - jbase;     // 10 or 11
    const int rows  = 4 * jc;           // gate rows owned by this block
    const int KIN   = (l == 0) ? I_ : H_;
    const int KTOT  = KIN + H_;
    const int tid   = threadIdx.x;

    // smem partition
    float* Wsm  = sm;                               // ROWS_MAX * KSTRIDE
    float* vbuf = Wsm  + ROWS_MAX * KSTRIDE;        // B * KSTRIDE   (concat [input | h_prev])
    float* acts = vbuf + B_ * KSTRIDE;              // ROWS_MAX * B
    float* csm  = acts + ROWS_MAX * B_;             // JC_MAX * B
    float* bsm  = csm  + JC_MAX * B_;               // ROWS_MAX

    // ---- load weights once (combined [Wih_row | Whh_row]) ----
    for (int e = tid; e < rows * KTOT; e += THREADS) {
        int r = e / KTOT;
        int k = e - r * KTOT;
        int gate = r / jc;
        int jl   = r - gate * jc;
        int g    = gate * H_ + jbase + jl;
        float w;
        if (k < KIN) {
            w = (l == 0) ? Wih0[(size_t)g * I_ + k]
                         : Wih[((size_t)(l - 1) * G4 + g) * H_ + k];
        } else {
            w = Whh[((size_t)l * G4 + g) * H_ + (k - KIN)];
        }
        Wsm[r * KSTRIDE + k] = w;
    }
    for (int r = tid; r < rows; r += THREADS) {
        int gate = r / jc;
        int jl   = r - gate * jc;
        int g    = gate * H_ + jbase + jl;
        bsm[r] = bih[l * G4 + g] + bhh[l * G4 + g];
    }
    // initial cell state slice
    for (int e = tid; e < jc * B_; e += THREADS) {
        int jl = e / B_;
        int b  = e - jl * B_;
        csm[e] = c0[((size_t)l * B_ + b) * H_ + jbase + jl];
    }
    __syncthreads();

    const int ntasks = rows * B_;
    volatile int* cnt = g_counter;

    for (int t = 0; t < T_; t++) {
        // ---- wait: own layer's previous h complete; input layer's step-t output ----
        if (tid == 0) {
            while (cnt[l * (T_ + 1) + t] < NBLK) { }
            if (l > 0) {
                while (cnt[(l - 1) * (T_ + 1) + t + 1] < NBLK) { }
            }
            __threadfence();
        }
        __syncthreads();

        // ---- build v = [input | h_prev] in smem ----
        {
            const float4* hp = (const float4*)(g_hseq +
                ((size_t)(l * (T_ + 1) + t)) * B_ * H_);
            for (int e = tid; e < B_ * (H_ / 4); e += THREADS) {
                int b  = e / (H_ / 4);
                int k4 = e - b * (H_ / 4);
                ((float4*)(vbuf + b * KSTRIDE + KIN))[k4] = hp[b * (H_ / 4) + k4];
            }
            if (l == 0) {
                const float4* xp = (const float4*)x;
                for (int e = tid; e < B_ * (I_ / 4); e += THREADS) {
                    int b  = e / (I_ / 4);
                    int k4 = e - b * (I_ / 4);
                    ((float4*)(vbuf + b * KSTRIDE))[k4] =
                        xp[((size_t)b * T_ + t) * (I_ / 4) + k4];
                }
            } else {
                const float4* ip = (const float4*)(g_hseq +
                    ((size_t)((l - 1) * (T_ + 1) + t + 1)) * B_ * H_);
                for (int e = tid; e < B_ * (H_ / 4); e += THREADS) {
                    int b  = e / (H_ / 4);
                    int k4 = e - b * (H_ / 4);
                    ((float4*)(vbuf + b * KSTRIDE))[k4] = ip[b * (H_ / 4) + k4];
                }
            }
        }
        __syncthreads();

        // ---- gate pre-activations: 440 dots of length KTOT ----
        for (int task = tid; task < ntasks; task += THREADS) {
            int r = task / B_;
            int b = task - r * B_;
            const float4* wr = (const float4*)(Wsm + r * KSTRIDE);
            const float4* vb = (const float4*)(vbuf + b * KSTRIDE);
            float acc = bsm[r];
            const int n4 = KTOT >> 2;
            #pragma unroll 4
            for (int k4 = 0; k4 < n4; k4++) {
                float4 w = wr[k4];
                float4 v = vb[k4];
                acc = fmaf(w.x, v.x, acc);
                acc = fmaf(w.y, v.y, acc);
                acc = fmaf(w.z, v.z, acc);
                acc = fmaf(w.w, v.w, acc);
            }
            acts[task] = acc;
        }
        __syncthreads();

        // ---- pointwise LSTM cell + publish h slice ----
        float* hout = g_hseq + ((size_t)(l * (T_ + 1) + t + 1)) * B_ * H_;
        for (int e = tid; e < jc * B_; e += THREADS) {
            int jl = e / B_;
            int b  = e - jl * B_;
            float ai = acts[(0 * jc + jl) * B_ + b];
            float af = acts[(1 * jc + jl) * B_ + b];
            float ag = acts[(2 * jc + jl) * B_ + b];
            float ao = acts[(3 * jc + jl) * B_ + b];
            float ig = sigmoidf_fast(ai);
            float fg = sigmoidf_fast(af);
            float gg = tanhf(ag);
            float og = sigmoidf_fast(ao);
            float c  = fmaf(fg, csm[e], ig * gg);
            csm[e] = c;
            hout[(size_t)b * H_ + jbase + jl] = og * tanhf(c);
        }
        __threadfence();
        __syncthreads();
        if (tid == 0) {
            atomicAdd(&g_counter[l * (T_ + 1) + t + 1], 1);
        }
    }

    // ---- final cell states -> out[L][B][H] ----
    for (int e = tid; e < jc * B_; e += THREADS) {
        int jl = e / B_;
        int b  = e - jl * B_;
        out[((size_t)l * B_ + b) * H_ + jbase + jl] = csm[e];
    }
}

#define SMEM_FLOATS (ROWS_MAX * KSTRIDE + B_ * KSTRIDE + ROWS_MAX * B_ + JC_MAX * B_ + ROWS_MAX)
#define SMEM_BYTES  (SMEM_FLOATS * (int)sizeof(float))

extern "C" void kernel_launch(void* const* d_in, const int* in_sizes, int n_in,
                              void* d_out, int out_size) {
    const float* x    = (const float*)d_in[0];
    const float* h0   = (const float*)d_in[1];
    const float* c0   = (const float*)d_in[2];
    const float* Wih0 = (const float*)d_in[3];
    const float* Wih  = (const float*)d_in[4];
    const float* Whh  = (const float*)d_in[5];
    const float* bih  = (const float*)d_in[6];
    const float* bhh  = (const float*)d_in[7];
    float* out = (float*)d_out;

    cudaFuncSetAttribute(lstm_pipeline_kernel,
                         cudaFuncAttributeMaxDynamicSharedMemorySize, SMEM_BYTES);

    lstm_init_kernel<<<64, 256>>>(h0);
    lstm_pipeline_kernel<<<L_ * NBLK, THREADS, SMEM_BYTES>>>(
        x, c0, Wih0, Wih, Whh, bih, bhh, out);
}

// round 2
// speedup vs baseline: 1.3787x; 1.3787x over previous
#include <cuda_runtime.h>
#include <math.h>

// Problem constants
#define B_  10
#define T_  2048
#define I_  128
#define H_  256
#define L_  6
#define G4  (4 * H_)      // 1024 gate rows per layer

// Kernel config
#define NBLK     24        // blocks per layer (6*24 = 144 <= 148 SMs, co-resident)
#define THREADS  256
#define KSTRIDE  524       // padded row stride (floats); 524 % 32 == 12 -> <=2-way conflicts
#define ROWS_MAX 44        // 4 * ceil(256/24)
#define JC_MAX   11

// Scratch (device globals: allocation-free contract)
// hseq[l][t][b][h] for t = 0..T (t=0 is h0)
__device__ float g_hseq[(size_t)L_ * (T_ + 1) * B_ * H_];
__device__ int   g_counter[L_ * (T_ + 1)];

__global__ void lstm_init_kernel(const float* __restrict__ h0) {
    int tid = blockIdx.x * blockDim.x + threadIdx.x;
    if (tid < L_ * B_ * H_) {
        int l = tid / (B_ * H_);
        int rem = tid - l * (B_ * H_);
        g_hseq[((size_t)l * (T_ + 1)) * B_ * H_ + rem] = h0[tid];
    }
    if (tid < L_ * (T_ + 1)) {
        g_counter[tid] = ((tid % (T_ + 1)) == 0) ? NBLK : 0;
    }
}

__device__ __forceinline__ float sigmoidf_fast(float x) {
    return 1.0f / (1.0f + __expf(-x));
}

__global__ void __launch_bounds__(THREADS, 1)
lstm_pipeline_kernel(const float* __restrict__ x,
                     const float* __restrict__ c0,
                     const float* __restrict__ Wih0,
                     const float* __restrict__ Wih,   // [L-1][4H][H]
                     const float* __restrict__ Whh,   // [L][4H][H]
                     const float* __restrict__ bih,   // [L][4H]
                     const float* __restrict__ bhh,   // [L][4H]
                     float* __restrict__ out)         // [L][B][H]
{
    extern __shared__ float sm[];

    const int l     = blockIdx.x / NBLK;
    const int p     = blockIdx.x % NBLK;
    const int jbase = (p * H_) / NBLK;
    const int jend  = ((p + 1) * H_) / NBLK;
    const int jc    = jend - jbase;     // 10 or 11
    const int rows  = 4 * jc;           // gate rows owned by this block
    const int KIN   = (l == 0) ? I_ : H_;
    const int KTOT  = KIN + H_;
    const int tid   = threadIdx.x;

    // smem partition
    float* Wsm  = sm;                               // ROWS_MAX * KSTRIDE
    float* vbuf = Wsm  + ROWS_MAX * KSTRIDE;        // B * KSTRIDE   (concat [input | h_prev])
    float* acts = vbuf + B_ * KSTRIDE;              // ROWS_MAX * B
    float* csm  = acts + ROWS_MAX * B_;             // JC_MAX * B
    float* bsm  = csm  + JC_MAX * B_;               // ROWS_MAX

    // ---- load weights once (combined [Wih_row | Whh_row]) ----
    for (int e = tid; e < rows * KTOT; e += THREADS) {
        int r = e / KTOT;
        int k = e - r * KTOT;
        int gate = r / jc;
        int jl   = r - gate * jc;
        int g    = gate * H_ + jbase + jl;
        float w;
        if (k < KIN) {
            w = (l == 0) ? Wih0[(size_t)g * I_ + k]
                         : Wih[((size_t)(l - 1) * G4 + g) * H_ + k];
        } else {
            w = Whh[((size_t)l * G4 + g) * H_ + (k - KIN)];
        }
        Wsm[r * KSTRIDE + k] = w;
    }
    for (int r = tid; r < rows; r += THREADS) {
        int gate = r / jc;
        int jl   = r - gate * jc;
        int g    = gate * H_ + jbase + jl;
        bsm[r] = bih[l * G4 + g] + bhh[l * G4 + g];
    }
    for (int e = tid; e < jc * B_; e += THREADS) {
        int jl = e / B_;
        int b  = e - jl * B_;
        csm[e] = c0[((size_t)l * B_ + b) * H_ + jbase + jl];
    }
    __syncthreads();

    const int npairs = 2 * jc * B_;     // each thread: rows (r0, r0+2jc), same b
    volatile int* cnt = g_counter;

    for (int t = 0; t < T_; t++) {
        // ---- wait: two flags polled from two different warps ----
        if (tid == 0) {
            while (cnt[l * (T_ + 1) + t] < NBLK) { }
        }
        if (tid == 32 && l > 0) {
            while (cnt[(l - 1) * (T_ + 1) + t + 1] < NBLK) { }
        }
        if (tid == 0) __threadfence();
        __syncthreads();

        // ---- build v = [input | h_prev] in smem ----
        {
            const float4* hp = (const float4*)(g_hseq +
                ((size_t)(l * (T_ + 1) + t)) * B_ * H_);
            for (int e = tid; e < B_ * (H_ / 4); e += THREADS) {
                int b  = e / (H_ / 4);
                int k4 = e - b * (H_ / 4);
                ((float4*)(vbuf + b * KSTRIDE + KIN))[k4] = hp[b * (H_ / 4) + k4];
            }
            if (l == 0) {
                const float4* xp = (const float4*)x;
                for (int e = tid; e < B_ * (I_ / 4); e += THREADS) {
                    int b  = e / (I_ / 4);
                    int k4 = e - b * (I_ / 4);
                    ((float4*)(vbuf + b * KSTRIDE))[k4] =
                        xp[((size_t)b * T_ + t) * (I_ / 4) + k4];
                }
            } else {
                const float4* ip = (const float4*)(g_hseq +
                    ((size_t)((l - 1) * (T_ + 1) + t + 1)) * B_ * H_);
                for (int e = tid; e < B_ * (H_ / 4); e += THREADS) {
                    int b  = e / (H_ / 4);
                    int k4 = e - b * (H_ / 4);
                    ((float4*)(vbuf + b * KSTRIDE))[k4] = ip[b * (H_ / 4) + k4];
                }
            }
        }
        __syncthreads();

        // ---- gate pre-activations: row-pair per thread, 4 indep accumulators ----
        if (tid < npairs) {
            const int r0 = tid / B_;              // 0 .. 2jc-1
            const int b  = tid - r0 * B_;
            const int r1 = r0 + 2 * jc;
            const float4* w0 = (const float4*)(Wsm + r0 * KSTRIDE);
            const float4* w1 = (const float4*)(Wsm + r1 * KSTRIDE);
            const float4* vb = (const float4*)(vbuf + b * KSTRIDE);
            float a00 = 0.f, a01 = 0.f, a10 = 0.f, a11 = 0.f;
            const int n4 = KTOT >> 2;             // 96 or 128, even
            #pragma unroll 4
            for (int k4 = 0; k4 < n4; k4 += 2) {
                float4 v0 = vb[k4];
                float4 v1 = vb[k4 + 1];
                float4 x0 = w0[k4];
                float4 x1 = w0[k4 + 1];
                float4 y0 = w1[k4];
                float4 y1 = w1[k4 + 1];
                a00 = fmaf(x0.x, v0.x, a00);
                a00 = fmaf(x0.y, v0.y, a00);
                a00 = fmaf(x0.z, v0.z, a00);
                a00 = fmaf(x0.w, v0.w, a00);
                a01 = fmaf(x1.x, v1.x, a01);
                a01 = fmaf(x1.y, v1.y, a01);
                a01 = fmaf(x1.z, v1.z, a01);
                a01 = fmaf(x1.w, v1.w, a01);
                a10 = fmaf(y0.x, v0.x, a10);
                a10 = fmaf(y0.y, v0.y, a10);
                a10 = fmaf(y0.z, v0.z, a10);
                a10 = fmaf(y0.w, v0.w, a10);
                a11 = fmaf(y1.x, v1.x, a11);
                a11 = fmaf(y1.y, v1.y, a11);
                a11 = fmaf(y1.z, v1.z, a11);
                a11 = fmaf(y1.w, v1.w, a11);
            }
            acts[r0 * B_ + b] = a00 + a01 + bsm[r0];
            acts[r1 * B_ + b] = a10 + a11 + bsm[r1];
        }
        __syncthreads();

        // ---- pointwise LSTM cell + publish h slice ----
        float* hout = g_hseq + ((size_t)(l * (T_ + 1) + t + 1)) * B_ * H_;
        for (int e = tid; e < jc * B_; e += THREADS) {
            int jl = e / B_;
            int b  = e - jl * B_;
            float ai = acts[(0 * jc + jl) * B_ + b];
            float af = acts[(1 * jc + jl) * B_ + b];
            float ag = acts[(2 * jc + jl) * B_ + b];
            float ao = acts[(3 * jc + jl) * B_ + b];
            float ig = sigmoidf_fast(ai);
            float fg = sigmoidf_fast(af);
            float gg = tanhf(ag);
            float og = sigmoidf_fast(ao);
            float c  = fmaf(fg, csm[e], ig * gg);
            csm[e] = c;
            hout[(size_t)b * H_ + jbase + jl] = og * tanhf(c);
        }
        __threadfence();
        __syncthreads();
        if (tid == 0) {
            atomicAdd(&g_counter[l * (T_ + 1) + t + 1], 1);
        }
    }

    // ---- final cell states -> out[L][B][H] ----
    for (int e = tid; e < jc * B_; e += THREADS) {
        int jl = e / B_;
        int b  = e - jl * B_;
        out[((size_t)l * B_ + b) * H_ + jbase + jl] = csm[e];
    }
}

#define SMEM_FLOATS (ROWS_MAX * KSTRIDE + B_ * KSTRIDE + ROWS_MAX * B_ + JC_MAX * B_ + ROWS_MAX)
#define SMEM_BYTES  (SMEM_FLOATS * (int)sizeof(float))

extern "C" void kernel_launch(void* const* d_in, const int* in_sizes, int n_in,
                              void* d_out, int out_size) {
    const float* x    = (const float*)d_in[0];
    const float* h0   = (const float*)d_in[1];
    const float* c0   = (const float*)d_in[2];
    const float* Wih0 = (const float*)d_in[3];
    const float* Wih  = (const float*)d_in[4];
    const float* Whh  = (const float*)d_in[5];
    const float* bih  = (const float*)d_in[6];
    const float* bhh  = (const float*)d_in[7];
    float* out = (float*)d_out;

    cudaFuncSetAttribute(lstm_pipeline_kernel,
                         cudaFuncAttributeMaxDynamicSharedMemorySize, SMEM_BYTES);

    lstm_init_kernel<<<64, 256>>>(h0);
    lstm_pipeline_kernel<<<L_ * NBLK, THREADS, SMEM_BYTES>>>(
        x, c0, Wih0, Wih, Whh, bih, bhh, out);
}